// round 1
// baseline (speedup 1.0000x reference)
#include <cuda_runtime.h>
#include <math.h>

#define BSZ  128
#define NTOK 196
#define CDIM 384
#define KB   16
#define HH   6
#define DR   96   // DIM/R
#define KH   96   // K*H

// scratch for softmaxed mixing coefficients, layout [B][N][K][H]
__device__ float g_mix[BSZ * NTOK * KH];

// ---------------------------------------------------------------------------
// Kernel 1: adapter MLP (Linear -> exact GELU -> Linear) + softmax over K
// ---------------------------------------------------------------------------
#define ROWS 32
#define TPB1 256

__global__ __launch_bounds__(TPB1, 2)
void adapter_kernel(const float* __restrict__ x,
                    const float* __restrict__ W1,
                    const float* __restrict__ b1,
                    const float* __restrict__ W2,
                    const float* __restrict__ b2)
{
    __shared__ float xs[ROWS][CDIM];    // 48 KB; reused as raw-mix buffer
    __shared__ float hid[ROWS][DR];     // 12 KB
    __shared__ float wst[DR * DR];      // 36 KB: W1 k-tile (32x96), then full W2

    const int t    = threadIdx.x;
    const int row0 = blockIdx.x * ROWS;

    // ---- load x tile (32 x 384), fully coalesced float4 ----
    {
        const float4* xg = (const float4*)(x + (size_t)row0 * CDIM);
        float4* xd = (float4*)&xs[0][0];
        for (int i = t; i < ROWS * CDIM / 4; i += TPB1) xd[i] = xg[i];
    }

    const int cg = t & 31;   // owns cols cg*3 + j   (j=0..2)
    const int rg = t >> 5;   // owns rows rg*4 + i   (i=0..3)  -> rg == warp id

    // ---- GEMM1: hid = x @ W1 + b1 ----
    float acc[4][3];
    #pragma unroll
    for (int i = 0; i < 4; i++)
        #pragma unroll
        for (int j = 0; j < 3; j++) acc[i][j] = b1[cg * 3 + j];

    for (int kt = 0; kt < CDIM; kt += 32) {
        __syncthreads();                       // protect wst overwrite
        for (int i = t; i < 32 * DR; i += TPB1) wst[i] = W1[kt * DR + i];
        __syncthreads();
        #pragma unroll
        for (int kk = 0; kk < 32; kk++) {
            float xv[4], wv[3];
            #pragma unroll
            for (int i = 0; i < 4; i++) xv[i] = xs[rg * 4 + i][kt + kk];
            #pragma unroll
            for (int j = 0; j < 3; j++) wv[j] = wst[kk * DR + cg * 3 + j];
            #pragma unroll
            for (int i = 0; i < 4; i++)
                #pragma unroll
                for (int j = 0; j < 3; j++) acc[i][j] += xv[i] * wv[j];
        }
    }

    // ---- exact GELU (erf form, torch/jax approximate=False) ----
    #pragma unroll
    for (int i = 0; i < 4; i++)
        #pragma unroll
        for (int j = 0; j < 3; j++) {
            float v = acc[i][j];
            hid[rg * 4 + i][cg * 3 + j] = 0.5f * v * (1.0f + erff(v * 0.70710678118654752f));
        }
    __syncthreads();                            // hid ready; GEMM1 reads of wst done

    // ---- GEMM2: mix_raw = hid @ W2 + b2 ----
    for (int i = t; i < DR * DR; i += TPB1) wst[i] = W2[i];
    __syncthreads();

    float acc2[4][3];
    #pragma unroll
    for (int i = 0; i < 4; i++)
        #pragma unroll
        for (int j = 0; j < 3; j++) acc2[i][j] = b2[cg * 3 + j];

    #pragma unroll 4
    for (int k = 0; k < DR; k++) {
        float xv[4], wv[3];
        #pragma unroll
        for (int i = 0; i < 4; i++) xv[i] = hid[rg * 4 + i][k];
        #pragma unroll
        for (int j = 0; j < 3; j++) wv[j] = wst[k * DR + cg * 3 + j];
        #pragma unroll
        for (int i = 0; i < 4; i++)
            #pragma unroll
            for (int j = 0; j < 3; j++) acc2[i][j] += xv[i] * wv[j];
    }

    // stash raw mix into (retired) xs buffer: mr[r*96 + c]
    float* mr = &xs[0][0];
    #pragma unroll
    for (int i = 0; i < 4; i++)
        #pragma unroll
        for (int j = 0; j < 3; j++)
            mr[(rg * 4 + i) * KH + cg * 3 + j] = acc2[i][j];
    __syncthreads();

    // ---- softmax over k (16 values, stride H) per (row, h); write g_mix ----
    if (t < ROWS * HH) {
        const int r = t / HH, h = t % HH;
        const float* p = mr + r * KH + h;
        float mx = -1e30f;
        #pragma unroll
        for (int k = 0; k < KB; k++) mx = fmaxf(mx, p[k * HH]);
        float e[KB], s = 0.0f;
        #pragma unroll
        for (int k = 0; k < KB; k++) { e[k] = expf(p[k * HH] - mx); s += e[k]; }
        const float inv = 1.0f / s;
        float* og = g_mix + (size_t)(row0 + r) * KH + h;
        #pragma unroll
        for (int k = 0; k < KB; k++) og[k * HH] = e[k] * inv;
    }
}

// ---------------------------------------------------------------------------
// Kernel 2: fused  weight[n,m,h] = sum_k mix[b,n,k,h]*WB[k,n,m]
//           then   out[b,m,h,c] += sum_n weight[n,m,h] * x[b,n,h,c]
// Block = (m-tile of 28, batch b). weight tile lives only in smem.
// ---------------------------------------------------------------------------
#define NT   28
#define MT   28
#define TPB2 384

__global__ __launch_bounds__(TPB2, 2)
void mix_kernel(const float* __restrict__ x,
                const float* __restrict__ WB,
                float* __restrict__ out)
{
    __shared__ float xs[NT][CDIM];      // 43 KB   x tile   [n][h*64+c]
    __shared__ float ws[NT][HH][MT];    // 18.4 KB weight   [n][h][m]
    __shared__ float ms[NT][KH];        // 10.5 KB mix tile [n][k*6+h]

    const int b  = blockIdx.y;
    const int m0 = blockIdx.x * MT;
    const int t  = threadIdx.x;

    const int h  = t / 64;        // 0..5
    const int u  = t % 64;
    const int mt = u / 16;        // 0..3 : m = mt + 4*i
    const int ct = u % 16;        // 0..15: c = ct*4 + j

    float acc[7][4];
    #pragma unroll
    for (int i = 0; i < 7; i++)
        #pragma unroll
        for (int j = 0; j < 4; j++) acc[i][j] = 0.0f;

    const float* xb = x     + (size_t)b * NTOK * CDIM;
    const float* mb = g_mix + (size_t)b * NTOK * KH;

    for (int n0 = 0; n0 < NTOK; n0 += NT) {
        // load x tile + mix tile (coalesced)
        {
            const float4* xg = (const float4*)(xb + (size_t)n0 * CDIM);
            float4* xd = (float4*)&xs[0][0];
            for (int i = t; i < NT * CDIM / 4; i += TPB2) xd[i] = xg[i];
            const float4* mg = (const float4*)(mb + (size_t)n0 * KH);
            float4* md = (float4*)&ms[0][0];
            for (int i = t; i < NT * KH / 4; i += TPB2) md[i] = mg[i];
        }
        __syncthreads();

        // build weight tile: ws[n][h][m] = sum_k ms[n][k*6+h] * WB[k][n0+n][m0+m]
        for (int p = t; p < NT * MT; p += TPB2) {
            const int n = p / MT, m = p % MT;
            const float* wbp = WB + (size_t)(n0 + n) * NTOK + (m0 + m);
            float w[HH] = {0, 0, 0, 0, 0, 0};
            #pragma unroll
            for (int k = 0; k < KB; k++) {
                const float wbv = __ldg(wbp + (size_t)k * NTOK * NTOK);
                const float* mp = &ms[n][k * HH];
                #pragma unroll
                for (int hh = 0; hh < HH; hh++) w[hh] += mp[hh] * wbv;
            }
            #pragma unroll
            for (int hh = 0; hh < HH; hh++) ws[n][hh][m] = w[hh];
        }
        __syncthreads();

        // accumulate: acc[i][j] += ws[n][h][mt+4i] * xs[n][h*64 + ct*4 + j]
        #pragma unroll 4
        for (int n = 0; n < NT; n++) {
            const float4 xv = *(const float4*)&xs[n][h * 64 + ct * 4];
            #pragma unroll
            for (int i = 0; i < 7; i++) {
                const float wv = ws[n][h][mt + 4 * i];
                acc[i][0] += wv * xv.x;
                acc[i][1] += wv * xv.y;
                acc[i][2] += wv * xv.z;
                acc[i][3] += wv * xv.w;
            }
        }
        __syncthreads();                // protect smem reuse next n-tile
    }

    // write out[b][m0+m][h*64 + ct*4 + j]
    #pragma unroll
    for (int i = 0; i < 7; i++) {
        const int m = m0 + mt + 4 * i;
        float4* o = (float4*)(out + ((size_t)b * NTOK + m) * CDIM + h * 64 + ct * 4);
        *o = make_float4(acc[i][0], acc[i][1], acc[i][2], acc[i][3]);
    }
}

// ---------------------------------------------------------------------------
extern "C" void kernel_launch(void* const* d_in, const int* in_sizes, int n_in,
                              void* d_out, int out_size)
{
    const float* x  = (const float*)d_in[0];
    const float* W1 = (const float*)d_in[1];
    const float* b1 = (const float*)d_in[2];
    const float* W2 = (const float*)d_in[3];
    const float* b2 = (const float*)d_in[4];
    const float* WB = (const float*)d_in[5];
    float* out = (float*)d_out;

    adapter_kernel<<<(BSZ * NTOK) / ROWS, TPB1>>>(x, W1, b1, W2, b2);
    mix_kernel<<<dim3(NTOK / MT, BSZ), TPB2>>>(x, WB, out);
}

// round 2
// speedup vs baseline: 1.0116x; 1.0116x over previous
#include <cuda_runtime.h>
#include <math.h>

#define BSZ  128
#define NTOK 196
#define CDIM 384
#define KB   16
#define HH   6
#define DR   96   // DIM/R
#define KH   96   // K*H

// scratch for softmaxed mixing coefficients, layout [B][N][K][H]
__device__ float g_mix[BSZ * NTOK * KH];

// ---------------------------------------------------------------------------
// Kernel 1: adapter MLP (Linear -> exact GELU -> Linear) + softmax over K
// ---------------------------------------------------------------------------
#define ROWS 32
#define TPB1 256

__global__ __launch_bounds__(TPB1, 2)
void adapter_kernel(const float* __restrict__ x,
                    const float* __restrict__ W1,
                    const float* __restrict__ b1,
                    const float* __restrict__ W2,
                    const float* __restrict__ b2)
{
    __shared__ float xs[ROWS][CDIM];    // 48 KB; reused as raw-mix buffer
    __shared__ float hid[ROWS][DR];     // 12 KB
    __shared__ float wst[DR * DR];      // 36 KB: W1 k-tile (32x96), then full W2

    const int t    = threadIdx.x;
    const int row0 = blockIdx.x * ROWS;

    // ---- load x tile (32 x 384), fully coalesced float4 ----
    {
        const float4* xg = (const float4*)(x + (size_t)row0 * CDIM);
        float4* xd = (float4*)&xs[0][0];
        for (int i = t; i < ROWS * CDIM / 4; i += TPB1) xd[i] = xg[i];
    }

    const int cg = t & 31;   // owns cols cg*3 + j   (j=0..2)
    const int rg = t >> 5;   // owns rows rg*4 + i   (i=0..3)  -> rg == warp id

    // ---- GEMM1: hid = x @ W1 + b1 ----
    float acc[4][3];
    #pragma unroll
    for (int i = 0; i < 4; i++)
        #pragma unroll
        for (int j = 0; j < 3; j++) acc[i][j] = b1[cg * 3 + j];

    for (int kt = 0; kt < CDIM; kt += 32) {
        __syncthreads();                       // protect wst overwrite
        for (int i = t; i < 32 * DR; i += TPB1) wst[i] = W1[kt * DR + i];
        __syncthreads();
        #pragma unroll
        for (int kk = 0; kk < 32; kk++) {
            float xv[4], wv[3];
            #pragma unroll
            for (int i = 0; i < 4; i++) xv[i] = xs[rg * 4 + i][kt + kk];
            #pragma unroll
            for (int j = 0; j < 3; j++) wv[j] = wst[kk * DR + cg * 3 + j];
            #pragma unroll
            for (int i = 0; i < 4; i++)
                #pragma unroll
                for (int j = 0; j < 3; j++) acc[i][j] += xv[i] * wv[j];
        }
    }

    // ---- exact GELU (erf form) ----
    #pragma unroll
    for (int i = 0; i < 4; i++)
        #pragma unroll
        for (int j = 0; j < 3; j++) {
            float v = acc[i][j];
            hid[rg * 4 + i][cg * 3 + j] = 0.5f * v * (1.0f + erff(v * 0.70710678118654752f));
        }
    __syncthreads();

    // ---- GEMM2: mix_raw = hid @ W2 + b2 ----
    for (int i = t; i < DR * DR; i += TPB1) wst[i] = W2[i];
    __syncthreads();

    float acc2[4][3];
    #pragma unroll
    for (int i = 0; i < 4; i++)
        #pragma unroll
        for (int j = 0; j < 3; j++) acc2[i][j] = b2[cg * 3 + j];

    #pragma unroll 4
    for (int k = 0; k < DR; k++) {
        float xv[4], wv[3];
        #pragma unroll
        for (int i = 0; i < 4; i++) xv[i] = hid[rg * 4 + i][k];
        #pragma unroll
        for (int j = 0; j < 3; j++) wv[j] = wst[k * DR + cg * 3 + j];
        #pragma unroll
        for (int i = 0; i < 4; i++)
            #pragma unroll
            for (int j = 0; j < 3; j++) acc2[i][j] += xv[i] * wv[j];
    }

    float* mr = &xs[0][0];
    #pragma unroll
    for (int i = 0; i < 4; i++)
        #pragma unroll
        for (int j = 0; j < 3; j++)
            mr[(rg * 4 + i) * KH + cg * 3 + j] = acc2[i][j];
    __syncthreads();

    // ---- softmax over k (16 values, stride H) per (row, h); write g_mix ----
    if (t < ROWS * HH) {
        const int r = t / HH, h = t % HH;
        const float* p = mr + r * KH + h;
        float mx = -1e30f;
        #pragma unroll
        for (int k = 0; k < KB; k++) mx = fmaxf(mx, p[k * HH]);
        float e[KB], s = 0.0f;
        #pragma unroll
        for (int k = 0; k < KB; k++) { e[k] = expf(p[k * HH] - mx); s += e[k]; }
        const float inv = 1.0f / s;
        float* og = g_mix + (size_t)(row0 + r) * KH + h;
        #pragma unroll
        for (int k = 0; k < KB; k++) og[k * HH] = e[k] * inv;
    }
}

// ---------------------------------------------------------------------------
// Kernel 2: fused  weight[n,m,h] = sum_k mix[b,n,k,h]*WB[k,n,m]
//           then   out[b,m,h,c] += sum_n weight[n,m,h] * x[b,n,h,c]
// Block = (m-tile of 28, batch b). 192 threads: warp == head h.
// Thread register tile: 7 m (contiguous) x 8 c (two float4).
// ---------------------------------------------------------------------------
#define NT   14
#define MT   28
#define TPB2 192

__global__ __launch_bounds__(TPB2, 3)
void mix_kernel(const float* __restrict__ x,
                const float* __restrict__ WB,
                float* __restrict__ out)
{
    __shared__ float xs[NT][CDIM];          // 21.5 KB  x tile  [n][h*64+c]
    __shared__ float ws2[NT][HH][32];       // 10.5 KB  weight  [n][h][mt*8+i], i<7
    __shared__ float ms[NT][KH];            //  5.25 KB mix     [n][k*6+h]

    const int b  = blockIdx.y;
    const int m0 = blockIdx.x * MT;
    const int t  = threadIdx.x;

    const int h    = t >> 5;          // warp id == head, 0..5
    const int lane = t & 31;
    const int mt   = lane >> 3;       // 0..3 : owns m = mt*7 + i, i=0..6
    const int ct   = lane & 7;        // 0..7 : owns c = ct*8 + j, j=0..7

    float acc[7][8];
    #pragma unroll
    for (int i = 0; i < 7; i++)
        #pragma unroll
        for (int j = 0; j < 8; j++) acc[i][j] = 0.0f;

    const float* xb = x     + (size_t)b * NTOK * CDIM;
    const float* mb = g_mix + (size_t)b * NTOK * KH;

    for (int n0 = 0; n0 < NTOK; n0 += NT) {
        // ---- load x tile + mix tile (coalesced float4) ----
        {
            const float4* xg = (const float4*)(xb + (size_t)n0 * CDIM);
            float4* xd = (float4*)&xs[0][0];
            #pragma unroll
            for (int i = t; i < NT * CDIM / 4; i += TPB2) xd[i] = xg[i];
            const float4* mg = (const float4*)(mb + (size_t)n0 * KH);
            float4* md = (float4*)&ms[0][0];
            for (int i = t; i < NT * KH / 4; i += TPB2) md[i] = mg[i];
        }
        __syncthreads();

        // ---- build weight tile: ws2[n][h][m] = sum_k ms[n][k*6+h]*WB[k][n0+n][m0+m]
        for (int p = t; p < NT * MT; p += TPB2) {
            const int n = p / MT, m = p % MT;
            const float* wbp = WB + (size_t)(n0 + n) * NTOK + (m0 + m);
            float w[HH] = {0, 0, 0, 0, 0, 0};
            #pragma unroll
            for (int k = 0; k < KB; k++) {
                const float wbv = __ldg(wbp + (size_t)k * NTOK * NTOK);
                const float* mp = &ms[n][k * HH];
                #pragma unroll
                for (int hh = 0; hh < HH; hh++) w[hh] += mp[hh] * wbv;
            }
            const int mg = m / 7, mi = m % 7;
            #pragma unroll
            for (int hh = 0; hh < HH; hh++) ws2[n][hh][mg * 8 + mi] = w[hh];
        }
        __syncthreads();

        // ---- accumulate: acc[i][j] += ws2[n][h][mt*8+i] * xs[n][h*64 + ct*8 + j]
        #pragma unroll 2
        for (int n = 0; n < NT; n++) {
            const float4* xrow = (const float4*)&xs[n][h * 64];
            const float4 xa = xrow[ct * 2];
            const float4 xb4 = xrow[ct * 2 + 1];
            const float* wbase = &ws2[n][h][mt * 8];
            const float4 w03 = *(const float4*)(wbase);
            const float2 w45 = *(const float2*)(wbase + 4);
            const float  w6  = wbase[6];
            float wv[7] = {w03.x, w03.y, w03.z, w03.w, w45.x, w45.y, w6};
            #pragma unroll
            for (int i = 0; i < 7; i++) {
                acc[i][0] += wv[i] * xa.x;
                acc[i][1] += wv[i] * xa.y;
                acc[i][2] += wv[i] * xa.z;
                acc[i][3] += wv[i] * xa.w;
                acc[i][4] += wv[i] * xb4.x;
                acc[i][5] += wv[i] * xb4.y;
                acc[i][6] += wv[i] * xb4.z;
                acc[i][7] += wv[i] * xb4.w;
            }
        }
        __syncthreads();                // protect smem reuse next n-tile
    }

    // ---- write out[b][m0 + mt*7 + i][h*64 + ct*8 + j] ----
    #pragma unroll
    for (int i = 0; i < 7; i++) {
        const int m = m0 + mt * 7 + i;
        float* o = out + ((size_t)b * NTOK + m) * CDIM + h * 64 + ct * 8;
        *(float4*)(o)     = make_float4(acc[i][0], acc[i][1], acc[i][2], acc[i][3]);
        *(float4*)(o + 4) = make_float4(acc[i][4], acc[i][5], acc[i][6], acc[i][7]);
    }
}

// ---------------------------------------------------------------------------
extern "C" void kernel_launch(void* const* d_in, const int* in_sizes, int n_in,
                              void* d_out, int out_size)
{
    const float* x  = (const float*)d_in[0];
    const float* W1 = (const float*)d_in[1];
    const float* b1 = (const float*)d_in[2];
    const float* W2 = (const float*)d_in[3];
    const float* b2 = (const float*)d_in[4];
    const float* WB = (const float*)d_in[5];
    float* out = (float*)d_out;

    adapter_kernel<<<(BSZ * NTOK) / ROWS, TPB1>>>(x, W1, b1, W2, b2);
    mix_kernel<<<dim3(NTOK / MT, BSZ), TPB2>>>(x, WB, out);
}

// round 3
// speedup vs baseline: 1.1632x; 1.1499x over previous
#include <cuda_runtime.h>
#include <math.h>
#include <stdint.h>

#define BSZ  128
#define NTOK 196
#define CDIM 384
#define KB   16
#define HH   6
#define DR   96   // DIM/R
#define KH   96   // K*H

// scratch for softmaxed mixing coefficients, layout [B][N][K][H]
__device__ __align__(256) float g_mix[BSZ * NTOK * KH];

// ---------------------------------------------------------------------------
// Kernel 1: adapter MLP (Linear -> exact GELU -> Linear) + softmax over K
// (unchanged from round 1)
// ---------------------------------------------------------------------------
#define ROWS 32
#define TPB1 256

__global__ __launch_bounds__(TPB1, 2)
void adapter_kernel(const float* __restrict__ x,
                    const float* __restrict__ W1,
                    const float* __restrict__ b1,
                    const float* __restrict__ W2,
                    const float* __restrict__ b2)
{
    __shared__ float xs[ROWS][CDIM];
    __shared__ float hid[ROWS][DR];
    __shared__ float wst[DR * DR];

    const int t    = threadIdx.x;
    const int row0 = blockIdx.x * ROWS;

    {
        const float4* xg = (const float4*)(x + (size_t)row0 * CDIM);
        float4* xd = (float4*)&xs[0][0];
        for (int i = t; i < ROWS * CDIM / 4; i += TPB1) xd[i] = xg[i];
    }

    const int cg = t & 31;
    const int rg = t >> 5;

    float acc[4][3];
    #pragma unroll
    for (int i = 0; i < 4; i++)
        #pragma unroll
        for (int j = 0; j < 3; j++) acc[i][j] = b1[cg * 3 + j];

    for (int kt = 0; kt < CDIM; kt += 32) {
        __syncthreads();
        for (int i = t; i < 32 * DR; i += TPB1) wst[i] = W1[kt * DR + i];
        __syncthreads();
        #pragma unroll
        for (int kk = 0; kk < 32; kk++) {
            float xv[4], wv[3];
            #pragma unroll
            for (int i = 0; i < 4; i++) xv[i] = xs[rg * 4 + i][kt + kk];
            #pragma unroll
            for (int j = 0; j < 3; j++) wv[j] = wst[kk * DR + cg * 3 + j];
            #pragma unroll
            for (int i = 0; i < 4; i++)
                #pragma unroll
                for (int j = 0; j < 3; j++) acc[i][j] += xv[i] * wv[j];
        }
    }

    #pragma unroll
    for (int i = 0; i < 4; i++)
        #pragma unroll
        for (int j = 0; j < 3; j++) {
            float v = acc[i][j];
            hid[rg * 4 + i][cg * 3 + j] = 0.5f * v * (1.0f + erff(v * 0.70710678118654752f));
        }
    __syncthreads();

    for (int i = t; i < DR * DR; i += TPB1) wst[i] = W2[i];
    __syncthreads();

    float acc2[4][3];
    #pragma unroll
    for (int i = 0; i < 4; i++)
        #pragma unroll
        for (int j = 0; j < 3; j++) acc2[i][j] = b2[cg * 3 + j];

    #pragma unroll 4
    for (int k = 0; k < DR; k++) {
        float xv[4], wv[3];
        #pragma unroll
        for (int i = 0; i < 4; i++) xv[i] = hid[rg * 4 + i][k];
        #pragma unroll
        for (int j = 0; j < 3; j++) wv[j] = wst[k * DR + cg * 3 + j];
        #pragma unroll
        for (int i = 0; i < 4; i++)
            #pragma unroll
            for (int j = 0; j < 3; j++) acc2[i][j] += xv[i] * wv[j];
    }

    float* mr = &xs[0][0];
    #pragma unroll
    for (int i = 0; i < 4; i++)
        #pragma unroll
        for (int j = 0; j < 3; j++)
            mr[(rg * 4 + i) * KH + cg * 3 + j] = acc2[i][j];
    __syncthreads();

    if (t < ROWS * HH) {
        const int r = t / HH, h = t % HH;
        const float* p = mr + r * KH + h;
        float mx = -1e30f;
        #pragma unroll
        for (int k = 0; k < KB; k++) mx = fmaxf(mx, p[k * HH]);
        float e[KB], s = 0.0f;
        #pragma unroll
        for (int k = 0; k < KB; k++) { e[k] = expf(p[k * HH] - mx); s += e[k]; }
        const float inv = 1.0f / s;
        float* og = g_mix + (size_t)(row0 + r) * KH + h;
        #pragma unroll
        for (int k = 0; k < KB; k++) og[k * HH] = e[k] * inv;
    }
}

// ---------------------------------------------------------------------------
// Kernel 2: fused weight-build + token mix.
// v3: cp.async.bulk double-buffered tiles, float4 WB loads, f32x2 FFMA2 core.
// ---------------------------------------------------------------------------
#define NT      14
#define MT      28
#define TPB2    192
#define NTILES  (NTOK / NT)       // 14

#define XS_F    (NT * CDIM)       // 5376 floats per buffer
#define MS_F    (NT * KH)         // 1344
#define WS_F    (NT * HH * 32)    // 2688
#define SMEM_F  (2 * XS_F + 2 * MS_F + WS_F)        // 16128 floats
#define SMEM_B  (SMEM_F * 4)                        // 64512 bytes
#define XBYTES  (XS_F * 4)        // 21504
#define MBYTES  (MS_F * 4)        // 5376

__device__ __forceinline__ uint32_t smem_u32(const void* p) {
    uint32_t a;
    asm("{ .reg .u64 t; cvta.to.shared.u64 t, %1; cvt.u32.u64 %0, t; }" : "=r"(a) : "l"(p));
    return a;
}

__global__ __launch_bounds__(TPB2, 3)
void mix_kernel(const float* __restrict__ x,
                const float* __restrict__ WB,
                float* __restrict__ out)
{
    extern __shared__ __align__(128) float sm[];
    float* xs0 = sm;                    // [2][NT][CDIM]
    float* ms0 = sm + 2 * XS_F;         // [2][NT][KH]
    float* ws  = sm + 2 * XS_F + 2 * MS_F;  // [NT][HH][32]
    __shared__ __align__(16) uint64_t mbar[2];

    const int b  = blockIdx.y;
    const int m0 = blockIdx.x * MT;
    const int t  = threadIdx.x;

    const int h    = t >> 5;          // warp == head
    const int lane = t & 31;
    const int mt   = lane >> 3;       // 0..3 : owns m = mt*7+i
    const int ct   = lane & 7;        // 0..7 : owns c = ct*8 + j (8 wide)

    const float* xb = x     + (size_t)b * NTOK * CDIM;
    const float* mb = g_mix + (size_t)b * NTOK * KH;

    // ---- mbarrier init + prologue bulk copy of tile 0 ----
    if (t == 0) {
        uint32_t m0a = smem_u32(&mbar[0]), m1a = smem_u32(&mbar[1]);
        asm volatile("mbarrier.init.shared.b64 [%0], 1;" :: "r"(m0a) : "memory");
        asm volatile("mbarrier.init.shared.b64 [%0], 1;" :: "r"(m1a) : "memory");
    }
    __syncthreads();

    if (t == 0) {
        uint32_t mba = smem_u32(&mbar[0]);
        asm volatile("mbarrier.arrive.expect_tx.shared.b64 _, [%0], %1;"
                     :: "r"(mba), "r"(XBYTES + MBYTES) : "memory");
        asm volatile("cp.async.bulk.shared::cta.global.mbarrier::complete_tx::bytes [%0], [%1], %2, [%3];"
                     :: "r"(smem_u32(xs0)), "l"(xb), "r"(XBYTES), "r"(mba) : "memory");
        asm volatile("cp.async.bulk.shared::cta.global.mbarrier::complete_tx::bytes [%0], [%1], %2, [%3];"
                     :: "r"(smem_u32(ms0)), "l"(mb), "r"(MBYTES), "r"(mba) : "memory");
    }

    uint64_t acc[7][4];
    #pragma unroll
    for (int i = 0; i < 7; i++)
        #pragma unroll
        for (int j = 0; j < 4; j++) acc[i][j] = 0ull;

    int ph0 = 0, ph1 = 0;

    for (int it = 0; it < NTILES; it++) {
        const int buf = it & 1;
        float* xsb = xs0 + buf * XS_F;
        float* msb = ms0 + buf * MS_F;

        // prefetch next tile into other buffer (its reads finished last iter)
        if (t == 0 && it + 1 < NTILES) {
            const int nb = buf ^ 1;
            uint32_t mba = smem_u32(&mbar[nb]);
            const float* xsrc = xb + (size_t)(it + 1) * NT * CDIM;
            const float* msrc = mb + (size_t)(it + 1) * NT * KH;
            asm volatile("mbarrier.arrive.expect_tx.shared.b64 _, [%0], %1;"
                         :: "r"(mba), "r"(XBYTES + MBYTES) : "memory");
            asm volatile("cp.async.bulk.shared::cta.global.mbarrier::complete_tx::bytes [%0], [%1], %2, [%3];"
                         :: "r"(smem_u32(xs0 + nb * XS_F)), "l"(xsrc), "r"(XBYTES), "r"(mba) : "memory");
            asm volatile("cp.async.bulk.shared::cta.global.mbarrier::complete_tx::bytes [%0], [%1], %2, [%3];"
                         :: "r"(smem_u32(ms0 + nb * MS_F)), "l"(msrc), "r"(MBYTES), "r"(mba) : "memory");
        }

        // wait for current buffer
        {
            uint32_t mba = smem_u32(&mbar[buf]);
            const int par = buf ? ph1 : ph0;
            uint32_t done;
            asm volatile(
                "{\n\t.reg .pred p;\n\t"
                "mbarrier.try_wait.parity.acquire.cta.shared::cta.b64 p, [%1], %2;\n\t"
                "selp.b32 %0, 1, 0, p;\n\t}"
                : "=r"(done) : "r"(mba), "r"(par) : "memory");
            if (!done) {
                asm volatile(
                    "{\n\t.reg .pred P1;\n\t"
                    "W_%=:\n\t"
                    "mbarrier.try_wait.parity.acquire.cta.shared::cta.b64 P1, [%0], %1, 0x989680;\n\t"
                    "@P1 bra.uni D_%=;\n\t"
                    "bra.uni W_%=;\n\t"
                    "D_%=:\n\t}"
                    :: "r"(mba), "r"(par) : "memory");
            }
            if (buf) ph1 ^= 1; else ph0 ^= 1;
        }

        // ---- build weight tile (vectorized over 4 m):
        //      ws[n][h][mg*8+mi] = sum_k ms[n][k*6+h] * WB[k][n0+n][m0+m]
        if (t < NT * (MT / 4)) {
            const int n    = t / (MT / 4);
            const int mvec = t % (MT / 4);
            const float4* wbp = (const float4*)(WB + (size_t)(it * NT + n) * NTOK + m0) + mvec;
            const float* mrow = msb + n * KH;
            float wacc[HH][4];
            #pragma unroll
            for (int hh = 0; hh < HH; hh++)
                #pragma unroll
                for (int j = 0; j < 4; j++) wacc[hh][j] = 0.0f;
            #pragma unroll
            for (int k = 0; k < KB; k++) {
                const float4 wb4 = __ldg(wbp + (size_t)k * (NTOK * NTOK / 4));
                const float2 m01 = *(const float2*)(mrow + k * HH);
                const float2 m23 = *(const float2*)(mrow + k * HH + 2);
                const float2 m45 = *(const float2*)(mrow + k * HH + 4);
                const float mk[HH] = {m01.x, m01.y, m23.x, m23.y, m45.x, m45.y};
                #pragma unroll
                for (int hh = 0; hh < HH; hh++) {
                    wacc[hh][0] += mk[hh] * wb4.x;
                    wacc[hh][1] += mk[hh] * wb4.y;
                    wacc[hh][2] += mk[hh] * wb4.z;
                    wacc[hh][3] += mk[hh] * wb4.w;
                }
            }
            #pragma unroll
            for (int j = 0; j < 4; j++) {
                const int m = mvec * 4 + j;
                const int mg = m / 7, mi = m % 7;
                #pragma unroll
                for (int hh = 0; hh < HH; hh++)
                    ws[(n * HH + hh) * 32 + mg * 8 + mi] = wacc[hh][j];
            }
        }
        __syncthreads();

        // ---- main contraction with packed f32x2 FMAs ----
        #pragma unroll 2
        for (int n = 0; n < NT; n++) {
            const float* xr = xsb + n * CDIM + h * 64 + ct * 8;
            const ulonglong2 xa = *(const ulonglong2*)xr;        // {c0c1},{c2c3}
            const ulonglong2 xc = *(const ulonglong2*)(xr + 4);  // {c4c5},{c6c7}
            const uint64_t xq[4] = {xa.x, xa.y, xc.x, xc.y};

            const float* wbase = ws + (n * HH + h) * 32 + mt * 8;
            const float4 w03 = *(const float4*)wbase;
            const float2 w45 = *(const float2*)(wbase + 4);
            const float  w6  = wbase[6];
            const float wv[7] = {w03.x, w03.y, w03.z, w03.w, w45.x, w45.y, w6};

            uint64_t wp[7];
            #pragma unroll
            for (int i = 0; i < 7; i++)
                asm("mov.b64 %0, {%1, %1};" : "=l"(wp[i]) : "f"(wv[i]));

            #pragma unroll
            for (int i = 0; i < 7; i++)
                #pragma unroll
                for (int j = 0; j < 4; j++)
                    asm("fma.rn.f32x2 %0, %1, %2, %0;"
                        : "+l"(acc[i][j]) : "l"(wp[i]), "l"(xq[j]));
        }
        __syncthreads();            // all reads of this buffer + ws done
    }

    // ---- unpack + write out[b][m0 + mt*7 + i][h*64 + ct*8 + j] ----
    #pragma unroll
    for (int i = 0; i < 7; i++) {
        const int m = m0 + mt * 7 + i;
        float* o = out + ((size_t)b * NTOK + m) * CDIM + h * 64 + ct * 8;
        float4 o1, o2;
        o1.x = __uint_as_float((uint32_t)(acc[i][0]));
        o1.y = __uint_as_float((uint32_t)(acc[i][0] >> 32));
        o1.z = __uint_as_float((uint32_t)(acc[i][1]));
        o1.w = __uint_as_float((uint32_t)(acc[i][1] >> 32));
        o2.x = __uint_as_float((uint32_t)(acc[i][2]));
        o2.y = __uint_as_float((uint32_t)(acc[i][2] >> 32));
        o2.z = __uint_as_float((uint32_t)(acc[i][3]));
        o2.w = __uint_as_float((uint32_t)(acc[i][3] >> 32));
        *(float4*)(o)     = o1;
        *(float4*)(o + 4) = o2;
    }
}

// ---------------------------------------------------------------------------
extern "C" void kernel_launch(void* const* d_in, const int* in_sizes, int n_in,
                              void* d_out, int out_size)
{
    const float* x  = (const float*)d_in[0];
    const float* W1 = (const float*)d_in[1];
    const float* b1 = (const float*)d_in[2];
    const float* W2 = (const float*)d_in[3];
    const float* b2 = (const float*)d_in[4];
    const float* WB = (const float*)d_in[5];
    float* out = (float*)d_out;

    cudaFuncSetAttribute(mix_kernel, cudaFuncAttributeMaxDynamicSharedMemorySize, SMEM_B);

    adapter_kernel<<<(BSZ * NTOK) / ROWS, TPB1>>>(x, W1, b1, W2, b2);
    mix_kernel<<<dim3(NTOK / MT, BSZ), TPB2, SMEM_B>>>(x, WB, out);
}